// round 9
// baseline (speedup 1.0000x reference)
#include <cuda_runtime.h>

// score[i] = sigmoid(logits[u[i] * V + v[i]]), V = 8192, B = 16384.
// Final kernel (= R5, best measured: 4.86us ncu / 5.76us dur).
// Structure locked by 8 rounds of measurement:
//  - scalar gather, 1 elem/thread, 256 blocks x 64 threads: maximizes warps
//    hiding the single dependent DRAM round-trip; ILP-2/4 variants measured
//    ~0.5us worse (within-LDG wavefront replays serialize on fewer warps).
//  - 32-bit addressing ((u<<13)|v, V*V = 2^26): no 64-bit IMAD chain.
//  - __expf + __fdividef epilogue: MUFU.EX2 + MUFU.RCP only. The full
//    precision 1/(1+e) division subroutine cost ~0.5us on the drain path
//    (the one verified real win of the session). rel_err ~5e-8 << 1e-3.
__global__ void __launch_bounds__(64, 32)
topos_gather_sigmoid(const int* __restrict__ u,
                     const int* __restrict__ v,
                     const float* __restrict__ logits,
                     float* __restrict__ out) {
    int i = blockIdx.x * 64 + threadIdx.x;
    int ui = __ldg(&u[i]);
    int vi = __ldg(&v[i]);
    float x = __ldg(logits + ((ui << 13) | vi));
    out[i] = __fdividef(1.0f, 1.0f + __expf(-x));
}

extern "C" void kernel_launch(void* const* d_in, const int* in_sizes, int n_in,
                              void* d_out, int out_size) {
    const int* u = (const int*)d_in[0];
    const int* v = (const int*)d_in[1];
    const float* logits = (const float*)d_in[2];
    float* out = (float*)d_out;

    const int B = in_sizes[0];  // 16384, multiple of 64
    topos_gather_sigmoid<<<B / 64, 64>>>(u, v, logits, out);
}

// round 10
// speedup vs baseline: 1.5105x; 1.5105x over previous
#include <cuda_runtime.h>

// score[i] = sigmoid(logits[u[i] * V + v[i]]), V = 8192, B = 16384.
// FINAL kernel (= R5 structure; best measured 4.86us ncu / 5.76us dur;
// identical binary re-measured at 5.31/6.91 -> harness noise is +/-0.6us).
//
// Locked-in structure, each element evidence-backed:
//  - Fused gather: only the 16384 requested table entries are touched
//    (2.2 MB total traffic vs 256+ MB for the materialized reference).
//  - Scalar, 1 elem/thread, 256 blocks x 64 threads: max warps hiding the
//    single dependent DRAM round-trip; ILP-2/4 variants measured no better
//    (within-LDG wavefront replays serialize on fewer warps).
//  - 32-bit addressing ((u<<13)|v, V*V = 2^26): no 64-bit IMAD chain
//    between index load and gather.
//  - __expf + __fdividef epilogue: MUFU.EX2 + MUFU.RCP only; the full
//    precision division subroutine measurably slowed the drain path.
//    rel_err ~5e-8, four orders under the 1e-3 gate.
// Remaining time is launch ramp + unramped DVFS clocks, not addressable
// from kernel code (all pipes <6%, issue ~1%, traffic at minimum).
__global__ void __launch_bounds__(64, 32)
topos_gather_sigmoid(const int* __restrict__ u,
                     const int* __restrict__ v,
                     const float* __restrict__ logits,
                     float* __restrict__ out) {
    int i = blockIdx.x * 64 + threadIdx.x;
    int ui = __ldg(&u[i]);
    int vi = __ldg(&v[i]);
    float x = __ldg(logits + ((ui << 13) | vi));
    out[i] = __fdividef(1.0f, 1.0f + __expf(-x));
}

extern "C" void kernel_launch(void* const* d_in, const int* in_sizes, int n_in,
                              void* d_out, int out_size) {
    const int* u = (const int*)d_in[0];
    const int* v = (const int*)d_in[1];
    const float* logits = (const float*)d_in[2];
    float* out = (float*)d_out;

    const int B = in_sizes[0];  // 16384, multiple of 64
    topos_gather_sigmoid<<<B / 64, 64>>>(u, v, logits, out);
}